// round 4
// baseline (speedup 1.0000x reference)
#include <cuda_runtime.h>
#include <cstddef>

#define N_NODES 50000
#define N_EDGES 800000
#define NUM_GRAPHS 256
#define IN_DIM 128
#define HDIM 64
#define HID 256
#define EPS_BN 1e-5f
#define SCAN_BLOCKS ((N_NODES + 1023) / 1024)

// ---------------- device scratch (no allocation allowed) ----------------
__device__ __align__(256) int   g_deg[N_NODES];
__device__ __align__(256) int   g_row_start[N_NODES + 1];
__device__ __align__(256) int   g_cursor[N_NODES];
__device__ __align__(256) int   g_csr[N_EDGES];
__device__ __align__(256) int   g_blocksum[64];
__device__ __align__(256) int   g_gstart[NUM_GRAPHS + 1];
__device__ __align__(256) float g_xl[N_NODES * HDIM];
__device__ __align__(256) float g_xr[N_NODES * HDIM];
__device__ __align__(256) float g_hA[N_NODES * HDIM];
__device__ __align__(256) float g_hB[N_NODES * HDIM];
__device__ __align__(256) float g_pooled[NUM_GRAPHS * HDIM];
__device__ __align__(256) float g_c1[NUM_GRAPHS * HID];
__device__ __align__(256) float g_c2[NUM_GRAPHS * (HID / 2)];
__device__ __align__(256) float g_c3[NUM_GRAPHS * (HID / 4)];
__device__ int g_ei64;   // 1 if edge_index is int64, 0 if int32
__device__ int g_b64;    // same for batch

// ---------------- dtype detection (int64 vs int32), all probes in-bounds ----
__global__ void detect_kernel(const void* ei, const void* batch) {
    if (threadIdx.x == 0 && blockIdx.x == 0) {
        const int* p = (const int*)ei;
        int is64 = 1;
        for (int i = 0; i < 64; i++) {
            if (p[2 * i + 1] != 0) { is64 = 0; break; }
        }
        g_ei64 = is64;
        // batch probes: int64-candidate indices [12500,12564) read int32 slots
        // < 25128 < 50000 -> in-bounds either way; sorted values there ~64-128.
        const int* pb = (const int*)batch;
        int b64 = 1;
        for (int i = 12500; i < 12564; i++) {
            if (pb[2 * i + 1] != 0) { b64 = 0; break; }
        }
        g_b64 = b64;
    }
}

__device__ __forceinline__ int idx_at(const void* p, long long i, int is64) {
    return is64 ? (int)((const long long*)p)[i] : ((const int*)p)[i];
}

// ---------------- CSR build ----------------
__global__ void zero_kernel() {
    int t = blockIdx.x * blockDim.x + threadIdx.x;
    if (t < N_NODES) { g_deg[t] = 0; g_cursor[t] = 0; }
}

__global__ void count_deg_kernel(const void* ei) {
    int e = blockIdx.x * blockDim.x + threadIdx.x;
    if (e >= N_EDGES) return;
    int is64 = g_ei64;
    int dst = idx_at(ei, (long long)N_EDGES + e, is64);
    atomicAdd(&g_deg[dst], 1);
}

// --- parallel scan: phase A (per-block inclusive scan) ---
__global__ void scanA_kernel() {
    __shared__ int s[1024];
    int tid = threadIdx.x;
    int idx = blockIdx.x * 1024 + tid;
    int v = (idx < N_NODES) ? g_deg[idx] : 0;
    s[tid] = v;
    __syncthreads();
#pragma unroll
    for (int off = 1; off < 1024; off <<= 1) {
        int t = (tid >= off) ? s[tid - off] : 0;
        __syncthreads();
        s[tid] += t;
        __syncthreads();
    }
    if (idx < N_NODES) g_row_start[idx + 1] = s[tid];
    if (tid == 1023) g_blocksum[blockIdx.x] = s[1023];
}

// --- phase B: scan the 49 block sums (1 block) ---
__global__ void scanB_kernel() {
    __shared__ int s[64];
    int tid = threadIdx.x;   // 64 threads
    int v = (tid < SCAN_BLOCKS) ? g_blocksum[tid] : 0;
    s[tid] = v;
    __syncthreads();
#pragma unroll
    for (int off = 1; off < 64; off <<= 1) {
        int t = (tid >= off) ? s[tid - off] : 0;
        __syncthreads();
        s[tid] += t;
        __syncthreads();
    }
    if (tid < SCAN_BLOCKS) g_blocksum[tid] = (tid > 0) ? s[tid - 1] : 0;
}

// --- phase C: add block offsets ---
__global__ void scanC_kernel() {
    int idx = blockIdx.x * blockDim.x + threadIdx.x;
    if (idx < N_NODES) g_row_start[idx + 1] += g_blocksum[idx >> 10];
    if (idx == 0) g_row_start[0] = 0;
}

__global__ void fill_csr_kernel(const void* ei) {
    int e = blockIdx.x * blockDim.x + threadIdx.x;
    if (e >= N_EDGES) return;
    int is64 = g_ei64;
    int src = idx_at(ei, e, is64);
    int dst = idx_at(ei, (long long)N_EDGES + e, is64);
    int pos = atomicAdd(&g_cursor[dst], 1);
    g_csr[g_row_start[dst] + pos] = src;
}

// ---------------- dual GEMM: (xl, xr) = h @ (Wl, Wr) ----------------
// 64-node x 128-col tiles (cols 0-63 -> xl, 64-127 -> xr), 256 threads,
// thread tile 4 nodes x 8 cols, K chunked by 32.
template <int K>
__global__ __launch_bounds__(256)
void gemm_dual_kernel(const float* __restrict__ h,
                      const float* __restrict__ Wl, const float* __restrict__ Wr,
                      float* __restrict__ xl, float* __restrict__ xr) {
    __shared__ float Hs[64 * 36];     // 64 nodes x 32 k, stride 36
    __shared__ float Ws[32 * 128];    // 32 k x 128 cols [Wl | Wr]

    int nb = blockIdx.x * 64;
    int tid = threadIdx.x;
    int tr = tid >> 4;       // 0..15 -> 4 nodes each
    int tc = tid & 15;       // 0..15 -> 8 cols each

    float acc[4][8];
#pragma unroll
    for (int i = 0; i < 4; i++)
#pragma unroll
        for (int j = 0; j < 8; j++) acc[i][j] = 0.0f;

    for (int k0 = 0; k0 < K; k0 += 32) {
        // load h tile: 64 nodes x 32 k = 512 float4
        for (int q = tid; q < 512; q += 256) {
            int n = q >> 3;
            int kq = q & 7;
            int gn = nb + n;
            float4 v = make_float4(0.f, 0.f, 0.f, 0.f);
            if (gn < N_NODES)
                v = *(const float4*)&h[(size_t)gn * K + k0 + kq * 4];
            *(float4*)&Hs[n * 36 + kq * 4] = v;
        }
        // load weights: 32 k x (64+64) cols = 1024 float4
        for (int q = tid; q < 1024; q += 256) {
            int k = q >> 5;          // 0..31
            int j4 = q & 31;         // 0..31 float4 within the 128-col row
            float4 w;
            if (j4 < 16)
                w = *(const float4*)&Wl[(size_t)(k0 + k) * 64 + j4 * 4];
            else
                w = *(const float4*)&Wr[(size_t)(k0 + k) * 64 + (j4 - 16) * 4];
            *(float4*)&Ws[k * 128 + j4 * 4] = w;
        }
        __syncthreads();

#pragma unroll
        for (int kk = 0; kk < 32; kk++) {
            float4 w0 = *(const float4*)&Ws[kk * 128 + tc * 8];
            float4 w1 = *(const float4*)&Ws[kk * 128 + tc * 8 + 4];
#pragma unroll
            for (int i = 0; i < 4; i++) {
                float a = Hs[(tr * 4 + i) * 36 + kk];
                acc[i][0] += a * w0.x;
                acc[i][1] += a * w0.y;
                acc[i][2] += a * w0.z;
                acc[i][3] += a * w0.w;
                acc[i][4] += a * w1.x;
                acc[i][5] += a * w1.y;
                acc[i][6] += a * w1.z;
                acc[i][7] += a * w1.w;
            }
        }
        __syncthreads();
    }

#pragma unroll
    for (int i = 0; i < 4; i++) {
        int gn = nb + tr * 4 + i;
        if (gn < N_NODES) {
            float* dst = (tc < 8) ? &xl[(size_t)gn * 64 + tc * 8]
                                  : &xr[(size_t)gn * 64 + (tc - 8) * 8];
            float4 o0 = make_float4(acc[i][0], acc[i][1], acc[i][2], acc[i][3]);
            float4 o1 = make_float4(acc[i][4], acc[i][5], acc[i][6], acc[i][7]);
            *(float4*)dst = o0;
            *(float4*)(dst + 4) = o1;
        }
    }
}

// ---------------- fused aggregate + combine ----------------
// out[n] = mean_{src in N(n)} xl[src] + bl + xr[n]   (all width 64, CH=16 float4)
__global__ void aggregate_combine_kernel(const float* __restrict__ xl,
                                         const float* __restrict__ xr,
                                         const float* __restrict__ bl,
                                         float* __restrict__ out) {
    int t = blockIdx.x * blockDim.x + threadIdx.x;
    if (t >= N_NODES * 16) return;
    int node = t >> 4;
    int c = t & 15;
    int s = g_row_start[node];
    int e = g_row_start[node + 1];
    const float4* xl4 = (const float4*)xl;
    float4 acc = make_float4(0.f, 0.f, 0.f, 0.f);
    for (int i = s; i < e; i++) {
        int sr = __ldg(&g_csr[i]);
        float4 v = __ldg(&xl4[(size_t)sr * 16 + c]);
        acc.x += v.x; acc.y += v.y; acc.z += v.z; acc.w += v.w;
    }
    float inv = 1.0f / fmaxf((float)(e - s), 1.0f);
    float4 b = __ldg(&((const float4*)bl)[c]);
    float4 r = __ldg(&((const float4*)xr)[t]);
    float4 o;
    o.x = acc.x * inv + b.x + r.x;
    o.y = acc.y * inv + b.y + r.y;
    o.z = acc.z * inv + b.z + r.z;
    o.w = acc.w * inv + b.w + r.w;
    ((float4*)out)[t] = o;
}

// ---------------- global mean pool (batch is sorted -> contiguous ranges) --
__global__ void graph_bounds_kernel(const void* __restrict__ batch) {
    int g = blockIdx.x * blockDim.x + threadIdx.x;
    if (g > NUM_GRAPHS) return;
    int b64 = g_b64;
    int lo = 0, hi = N_NODES;
    while (lo < hi) {
        int mid = (lo + hi) >> 1;
        if (idx_at(batch, mid, b64) < g) lo = mid + 1; else hi = mid;
    }
    g_gstart[g] = lo;
}

// one block per graph, 64 threads (one per feature), coalesced reduction
__global__ void pool_kernel(const float* __restrict__ h) {
    int g = blockIdx.x;
    int f = threadIdx.x;
    int s = g_gstart[g];
    int e = g_gstart[g + 1];
    float acc = 0.0f;
    for (int i = s; i < e; i++)
        acc += h[(size_t)i * HDIM + f];
    g_pooled[g * HDIM + f] = acc / fmaxf((float)(e - s), 1.0f);
}

// ---------------- MLP head ----------------
__global__ void lin_kernel(const float* __restrict__ in, const float* __restrict__ W,
                           const float* __restrict__ b, float* __restrict__ out,
                           int Kdim, int Jdim) {
    int t = blockIdx.x * blockDim.x + threadIdx.x;
    if (t >= NUM_GRAPHS * Jdim) return;
    int g = t / Jdim;
    int j = t % Jdim;
    float acc = b[j];
    for (int k = 0; k < Kdim; k++)
        acc += __ldg(&in[g * Kdim + k]) * __ldg(&W[k * Jdim + j]);
    out[t] = acc;
}

__device__ __forceinline__ float blkred256(float v) {
    __shared__ float sh[256];
    int tid = threadIdx.x;
    sh[tid] = v;
    __syncthreads();
    for (int o = 128; o > 0; o >>= 1) {
        if (tid < o) sh[tid] += sh[tid + o];
        __syncthreads();
    }
    float r = sh[0];
    __syncthreads();
    return r;
}

// one block per column, 256 threads = 256 graph rows; training-mode BN + tanh
__global__ void bn_tanh_kernel(float* __restrict__ c, const float* __restrict__ gamma,
                               const float* __restrict__ beta, int Jdim) {
    int col = blockIdx.x;
    int r = threadIdx.x;
    float v = c[r * Jdim + col];
    float s = blkred256(v);
    __shared__ float mean_s;
    if (r == 0) mean_s = s * (1.0f / NUM_GRAPHS);
    __syncthreads();
    float d = v - mean_s;
    float s2 = blkred256(d * d);
    __shared__ float inv_s;
    if (r == 0) inv_s = rsqrtf(s2 * (1.0f / NUM_GRAPHS) + EPS_BN);
    __syncthreads();
    c[r * Jdim + col] = tanhf(d * inv_s * gamma[col] + beta[col]);
}

// ---------------- launcher ----------------
extern "C" void kernel_launch(void* const* d_in, const int* in_sizes, int n_in,
                              void* d_out, int out_size) {
    const float* x       = (const float*)d_in[0];
    const void*  ei      = d_in[1];
    const void*  batch   = d_in[2];
    const float* W1l     = (const float*)d_in[3];
    const float* b1l     = (const float*)d_in[4];
    const float* W1r     = (const float*)d_in[5];
    const float* W2l     = (const float*)d_in[6];
    const float* b2l     = (const float*)d_in[7];
    const float* W2r     = (const float*)d_in[8];
    const float* W3l     = (const float*)d_in[9];
    const float* b3l     = (const float*)d_in[10];
    const float* W3r     = (const float*)d_in[11];
    const float* lin1_w  = (const float*)d_in[12];
    const float* lin1_b  = (const float*)d_in[13];
    const float* g1      = (const float*)d_in[14];
    const float* be1     = (const float*)d_in[15];
    const float* lin2_w  = (const float*)d_in[16];
    const float* lin2_b  = (const float*)d_in[17];
    const float* g2      = (const float*)d_in[18];
    const float* be2     = (const float*)d_in[19];
    const float* lin3_w  = (const float*)d_in[20];
    const float* lin3_b  = (const float*)d_in[21];
    const float* g3      = (const float*)d_in[22];
    const float* be3     = (const float*)d_in[23];
    const float* lin4_w  = (const float*)d_in[24];
    const float* lin4_b  = (const float*)d_in[25];
    float* out = (float*)d_out;

    float *xl, *xr, *hA, *hB, *pooled, *c1, *c2, *c3;
    cudaGetSymbolAddress((void**)&xl,     g_xl);
    cudaGetSymbolAddress((void**)&xr,     g_xr);
    cudaGetSymbolAddress((void**)&hA,     g_hA);
    cudaGetSymbolAddress((void**)&hB,     g_hB);
    cudaGetSymbolAddress((void**)&pooled, g_pooled);
    cudaGetSymbolAddress((void**)&c1,     g_c1);
    cudaGetSymbolAddress((void**)&c2,     g_c2);
    cudaGetSymbolAddress((void**)&c3,     g_c3);

    const int NTILE = (N_NODES + 63) / 64;
    const int AGG_BLOCKS = (N_NODES * 16 + 255) / 256;

    detect_kernel<<<1, 32>>>(ei, batch);
    zero_kernel<<<(N_NODES + 255) / 256, 256>>>();
    count_deg_kernel<<<(N_EDGES + 255) / 256, 256>>>(ei);
    scanA_kernel<<<SCAN_BLOCKS, 1024>>>();
    scanB_kernel<<<1, 64>>>();
    scanC_kernel<<<(N_NODES + 255) / 256, 256>>>();
    fill_csr_kernel<<<(N_EDGES + 255) / 256, 256>>>(ei);

    // layer 1: project first (linearity of mean aggregation), then aggregate at width 64
    gemm_dual_kernel<IN_DIM><<<NTILE, 256>>>(x, W1l, W1r, xl, xr);
    aggregate_combine_kernel<<<AGG_BLOCKS, 256>>>(xl, xr, b1l, hA);

    // layer 2
    gemm_dual_kernel<HDIM><<<NTILE, 256>>>(hA, W2l, W2r, xl, xr);
    aggregate_combine_kernel<<<AGG_BLOCKS, 256>>>(xl, xr, b2l, hB);

    // layer 3
    gemm_dual_kernel<HDIM><<<NTILE, 256>>>(hB, W3l, W3r, xl, xr);
    aggregate_combine_kernel<<<AGG_BLOCKS, 256>>>(xl, xr, b3l, hA);

    // global mean pool (sorted batch -> contiguous per-graph ranges, no atomics)
    graph_bounds_kernel<<<2, 256>>>(batch);
    pool_kernel<<<NUM_GRAPHS, HDIM>>>(hA);

    // MLP head with training-mode BN + tanh
    lin_kernel<<<(NUM_GRAPHS * HID + 255) / 256, 256>>>(pooled, lin1_w, lin1_b, c1, HDIM, HID);
    bn_tanh_kernel<<<HID, 256>>>(c1, g1, be1, HID);
    lin_kernel<<<(NUM_GRAPHS * (HID / 2) + 255) / 256, 256>>>(c1, lin2_w, lin2_b, c2, HID, HID / 2);
    bn_tanh_kernel<<<HID / 2, 256>>>(c2, g2, be2, HID / 2);
    lin_kernel<<<(NUM_GRAPHS * (HID / 4) + 255) / 256, 256>>>(c2, lin3_w, lin3_b, c3, HID / 2, HID / 4);
    bn_tanh_kernel<<<HID / 4, 256>>>(c3, g3, be3, HID / 4);
    lin_kernel<<<(NUM_GRAPHS * 10 + 255) / 256, 256>>>(c3, lin4_w, lin4_b, out, HID / 4, 10);
}